// round 5
// baseline (speedup 1.0000x reference)
#include <cuda_runtime.h>
#include <math.h>

#define N_BATCH 32
#define C_IN    256
#define C_SQ    64
#define HW      12544              // 112*112
#define HW4     3136               // HW/4 float4 per plane
#define PLANES  (N_BATCH * C_IN)   // 8192
#define TPB     448                // 448 * 7 == 3136 exactly
#define VPT     7                  // float4 per thread (scale kernel)

// Scratch (no allocations allowed)
__device__ float g_pool[PLANES];

// ---------------------------------------------------------------------------
// Kernel 1: global average pool. One block per (n,c) plane, 256 threads,
// strided float4 loop, default cache policy (leaves the tail L2-resident for
// the reversed-order scale kernel).
// ---------------------------------------------------------------------------
__global__ __launch_bounds__(256) void se_pool_kernel(
    const float* __restrict__ x)
{
    const int plane = blockIdx.x;
    const float4* p = reinterpret_cast<const float4*>(x + (size_t)plane * HW);

    float sum = 0.0f;
    #pragma unroll 4
    for (int i = threadIdx.x; i < HW4; i += 256) {
        float4 v = p[i];
        sum += (v.x + v.y) + (v.z + v.w);
    }

    #pragma unroll
    for (int off = 16; off > 0; off >>= 1)
        sum += __shfl_down_sync(0xFFFFFFFFu, sum, off);

    __shared__ float warp_sums[8];
    const int lane = threadIdx.x & 31;
    const int wid  = threadIdx.x >> 5;
    if (lane == 0) warp_sums[wid] = sum;
    __syncthreads();

    if (wid == 0) {
        float s = (lane < 8) ? warp_sums[lane] : 0.0f;
        #pragma unroll
        for (int off = 4; off > 0; off >>= 1)
            s += __shfl_down_sync(0xFFFFFFFFu, s, off);
        if (lane == 0)
            g_pool[plane] = s * (1.0f / (float)HW);
    }
}

// ---------------------------------------------------------------------------
// Kernel 2 (fused MLP + scale): one block per plane, reversed order.
// 1) Front-batch the 7 x-plane LDG.128s (independent of the gate).
// 2) Under their load shadow, redundantly compute this batch's gate from
//    g_pool: threads 0-63 each compute one s_red entry (256-FMA dot + ReLU),
//    then every thread computes the expand dot for this plane's channel.
// 3) Multiply and stream the results out.
// ---------------------------------------------------------------------------
__global__ __launch_bounds__(TPB) void se_scale_kernel(
    const float* __restrict__ x,
    float*       __restrict__ out,
    const float* __restrict__ w_reduce,   // [C_SQ, C_IN]
    const float* __restrict__ b_reduce,   // [C_SQ]
    const float* __restrict__ w_expand,   // [C_IN, C_SQ]
    const float* __restrict__ b_expand)   // [C_IN]
{
    const int plane = (PLANES - 1) - blockIdx.x;   // reverse order for L2 reuse
    const int n = plane >> 8;        // batch
    const int c = plane & 255;       // channel
    const int tid = threadIdx.x;

    const float4* p = reinterpret_cast<const float4*>(x   + (size_t)plane * HW);
    float4*       q = reinterpret_cast<float4*>(out       + (size_t)plane * HW);

    // 1) issue plane loads first — everything below hides under their latency
    float4 v[VPT];
    #pragma unroll
    for (int i = 0; i < VPT; i++)
        v[i] = p[tid + i * TPB];

    // 2) gate compute (redundant per block, hidden under load shadow)
    __shared__ float s_pool[C_IN];
    __shared__ float s_red[C_SQ];

    if (tid < C_IN) s_pool[tid] = g_pool[n * C_IN + tid];
    __syncthreads();

    if (tid < C_SQ) {
        float a0 = b_reduce[tid], a1 = 0.f, a2 = 0.f, a3 = 0.f;
        const float* wr = w_reduce + tid * C_IN;
        #pragma unroll 4
        for (int k = 0; k < C_IN; k += 4) {
            a0 = fmaf(wr[k + 0], s_pool[k + 0], a0);
            a1 = fmaf(wr[k + 1], s_pool[k + 1], a1);
            a2 = fmaf(wr[k + 2], s_pool[k + 2], a2);
            a3 = fmaf(wr[k + 3], s_pool[k + 3], a3);
        }
        s_red[tid] = fmaxf((a0 + a1) + (a2 + a3), 0.0f);
    }
    __syncthreads();

    float acc = b_expand[c];
    const float* we = w_expand + c * C_SQ;
    #pragma unroll 8
    for (int k = 0; k < C_SQ; k++)
        acc = fmaf(we[k], s_red[k], acc);
    const float g = 1.0f / (1.0f + __expf(-acc));

    // 3) scale + streaming stores
    #pragma unroll
    for (int i = 0; i < VPT; i++) {
        v[i].x *= g; v[i].y *= g; v[i].z *= g; v[i].w *= g;
        __stcs(&q[tid + i * TPB], v[i]);
    }
}

// ---------------------------------------------------------------------------
extern "C" void kernel_launch(void* const* d_in, const int* in_sizes, int n_in,
                              void* d_out, int out_size)
{
    const float* x        = (const float*)d_in[0];
    const float* w_reduce = (const float*)d_in[1];
    const float* b_reduce = (const float*)d_in[2];
    const float* w_expand = (const float*)d_in[3];
    const float* b_expand = (const float*)d_in[4];
    float* out = (float*)d_out;

    se_pool_kernel<<<PLANES, 256>>>(x);
    se_scale_kernel<<<PLANES, TPB>>>(x, out, w_reduce, b_reduce,
                                     w_expand, b_expand);
}

// round 6
// speedup vs baseline: 1.8066x; 1.8066x over previous
#include <cuda_runtime.h>
#include <math.h>

#define N_BATCH 32
#define C_IN    256
#define C_SQ    64
#define HW      12544              // 112*112
#define HW4     3136               // HW/4 float4 per plane
#define PLANES  (N_BATCH * C_IN)   // 8192
#define TPB     448                // 448 * 7 == 3136 exactly
#define VPT     7                  // float4 per thread (scale kernel)

#define BATCH_PER_GROUP 4
#define GROUPS          (N_BATCH / BATCH_PER_GROUP)      // 8
#define PLANES_PER_GRP  (BATCH_PER_GROUP * C_IN)         // 1024

// Scratch (no allocations allowed)
__device__ float g_pool[PLANES];
__device__ float g_gate[PLANES];

// ---------------------------------------------------------------------------
// Pool: one block per plane within the group. Default cache policy so the
// group's 51.2 MB stays resident in L2 for the scale pass.
// ---------------------------------------------------------------------------
__global__ __launch_bounds__(256) void se_pool_kernel(
    const float* __restrict__ x, int plane_base)
{
    const int plane = plane_base + blockIdx.x;
    const float4* p = reinterpret_cast<const float4*>(x + (size_t)plane * HW);

    float sum = 0.0f;
    #pragma unroll 4
    for (int i = threadIdx.x; i < HW4; i += 256) {
        float4 v = p[i];
        sum += (v.x + v.y) + (v.z + v.w);
    }

    #pragma unroll
    for (int off = 16; off > 0; off >>= 1)
        sum += __shfl_down_sync(0xFFFFFFFFu, sum, off);

    __shared__ float warp_sums[8];
    const int lane = threadIdx.x & 31;
    const int wid  = threadIdx.x >> 5;
    if (lane == 0) warp_sums[wid] = sum;
    __syncthreads();

    if (wid == 0) {
        float s = (lane < 8) ? warp_sums[lane] : 0.0f;
        #pragma unroll
        for (int off = 4; off > 0; off >>= 1)
            s += __shfl_down_sync(0xFFFFFFFFu, s, off);
        if (lane == 0)
            g_pool[plane] = s * (1.0f / (float)HW);
    }
}

// ---------------------------------------------------------------------------
// MLP: one block per batch element of the group (BATCH_PER_GROUP blocks).
// ---------------------------------------------------------------------------
__global__ __launch_bounds__(256) void se_mlp_kernel(
    const float* __restrict__ w_reduce,   // [C_SQ, C_IN]
    const float* __restrict__ b_reduce,   // [C_SQ]
    const float* __restrict__ w_expand,   // [C_IN, C_SQ]
    const float* __restrict__ b_expand,   // [C_IN]
    int batch_base)
{
    const int n   = batch_base + blockIdx.x;
    const int tid = threadIdx.x;

    __shared__ float s_in[C_IN];
    __shared__ float s_red[C_SQ];

    s_in[tid] = g_pool[n * C_IN + tid];
    __syncthreads();

    if (tid < C_SQ) {
        float acc = b_reduce[tid];
        const float* wr = w_reduce + tid * C_IN;
        #pragma unroll 8
        for (int c = 0; c < C_IN; c++)
            acc = fmaf(wr[c], s_in[c], acc);
        s_red[tid] = fmaxf(acc, 0.0f);
    }
    __syncthreads();

    float acc = b_expand[tid];
    const float* we = w_expand + tid * C_SQ;
    #pragma unroll 8
    for (int k = 0; k < C_SQ; k++)
        acc = fmaf(we[k], s_red[k], acc);

    g_gate[n * C_IN + tid] = 1.0f / (1.0f + __expf(-acc));
}

// ---------------------------------------------------------------------------
// Scale: one block per plane within the group. Reads should hit L2 (group
// was just read by pool). 448 threads x 7 float4, loads front-batched,
// streaming stores (evict-first) so writes don't evict the read set.
// ---------------------------------------------------------------------------
__global__ __launch_bounds__(TPB) void se_scale_kernel(
    const float* __restrict__ x,
    float*       __restrict__ out,
    int plane_base)
{
    const int plane = plane_base + blockIdx.x;
    const float g = __ldg(&g_gate[plane]);

    const float4* p = reinterpret_cast<const float4*>(x   + (size_t)plane * HW);
    float4*       q = reinterpret_cast<float4*>(out       + (size_t)plane * HW);

    float4 v[VPT];
    #pragma unroll
    for (int i = 0; i < VPT; i++)
        v[i] = p[threadIdx.x + i * TPB];

    #pragma unroll
    for (int i = 0; i < VPT; i++) {
        v[i].x *= g; v[i].y *= g; v[i].z *= g; v[i].w *= g;
        __stcs(&q[threadIdx.x + i * TPB], v[i]);
    }
}

// ---------------------------------------------------------------------------
extern "C" void kernel_launch(void* const* d_in, const int* in_sizes, int n_in,
                              void* d_out, int out_size)
{
    const float* x        = (const float*)d_in[0];
    const float* w_reduce = (const float*)d_in[1];
    const float* b_reduce = (const float*)d_in[2];
    const float* w_expand = (const float*)d_in[3];
    const float* b_expand = (const float*)d_in[4];
    float* out = (float*)d_out;

    for (int g = 0; g < GROUPS; g++) {
        const int plane_base = g * PLANES_PER_GRP;
        const int batch_base = g * BATCH_PER_GROUP;

        se_pool_kernel<<<PLANES_PER_GRP, 256>>>(x, plane_base);
        se_mlp_kernel<<<BATCH_PER_GROUP, 256>>>(w_reduce, b_reduce,
                                                w_expand, b_expand, batch_base);
        se_scale_kernel<<<PLANES_PER_GRP, TPB>>>(x, out, plane_base);
    }
}

// round 7
// speedup vs baseline: 2.9826x; 1.6510x over previous
#include <cuda_runtime.h>
#include <math.h>

#define N_BATCH 32
#define C_IN    256
#define C_SQ    64
#define HW      12544              // 112*112
#define HW4     3136               // HW/4 float4 per plane
#define PLANES  (N_BATCH * C_IN)   // 8192
#define TPB     448                // 448 * 7 == 3136 exactly
#define VPT     7                  // float4 per thread (scale kernel)

// Scratch (no allocations allowed)
__device__ float g_pool[PLANES];
__device__ float g_gate[PLANES];
__device__ unsigned g_cnt[N_BATCH];   // zero-initialized; self-resetting

// ---------------------------------------------------------------------------
// Kernel 1: global average pool + fused MLP tail.
// One block per (n,c) plane, 256 threads, strided float4 loop.
// After writing its plane mean, each block arrives on its batch's counter;
// the last arriver (threadfence-reduction pattern) computes the whole MLP
// for that batch and writes the 256 gates, then resets the counter so the
// kernel is graph-replayable.
// ---------------------------------------------------------------------------
__global__ __launch_bounds__(256) void se_pool_mlp_kernel(
    const float* __restrict__ x,
    const float* __restrict__ w_reduce,   // [C_SQ, C_IN]
    const float* __restrict__ b_reduce,   // [C_SQ]
    const float* __restrict__ w_expand,   // [C_IN, C_SQ]
    const float* __restrict__ b_expand)   // [C_IN]
{
    const int plane = blockIdx.x;
    const int n     = plane >> 8;
    const int tid   = threadIdx.x;
    const float4* p = reinterpret_cast<const float4*>(x + (size_t)plane * HW);

    float sum = 0.0f;
    #pragma unroll 4
    for (int i = tid; i < HW4; i += 256) {
        float4 v = p[i];
        sum += (v.x + v.y) + (v.z + v.w);
    }

    #pragma unroll
    for (int off = 16; off > 0; off >>= 1)
        sum += __shfl_down_sync(0xFFFFFFFFu, sum, off);

    __shared__ float warp_sums[8];
    __shared__ int   s_amlast;
    const int lane = tid & 31;
    const int wid  = tid >> 5;
    if (lane == 0) warp_sums[wid] = sum;
    __syncthreads();

    if (tid == 0) {
        float s = 0.0f;
        #pragma unroll
        for (int w = 0; w < 8; w++) s += warp_sums[w];
        g_pool[plane] = s * (1.0f / (float)HW);
        __threadfence();                       // make mean visible before arrive
        unsigned old = atomicAdd(&g_cnt[n], 1u);
        s_amlast = (old == 255u);
    }
    __syncthreads();

    if (!s_amlast) return;

    // ---- last block of batch n: compute the MLP for this batch ----
    __shared__ float s_in[C_IN];
    __shared__ float s_red[C_SQ];

    s_in[tid] = __ldcg(&g_pool[n * C_IN + tid]);   // L2 reads (bypass L1)
    __syncthreads();

    if (tid < C_SQ) {
        float a0 = b_reduce[tid], a1 = 0.f, a2 = 0.f, a3 = 0.f;
        const float* wr = w_reduce + tid * C_IN;
        #pragma unroll 4
        for (int k = 0; k < C_IN; k += 4) {
            a0 = fmaf(wr[k + 0], s_in[k + 0], a0);
            a1 = fmaf(wr[k + 1], s_in[k + 1], a1);
            a2 = fmaf(wr[k + 2], s_in[k + 2], a2);
            a3 = fmaf(wr[k + 3], s_in[k + 3], a3);
        }
        s_red[tid] = fmaxf((a0 + a1) + (a2 + a3), 0.0f);
    }
    __syncthreads();

    float acc = b_expand[tid];
    const float* we = w_expand + tid * C_SQ;
    #pragma unroll 8
    for (int k = 0; k < C_SQ; k++)
        acc = fmaf(we[k], s_red[k], acc);

    g_gate[n * C_IN + tid] = 1.0f / (1.0f + __expf(-acc));

    __syncthreads();
    if (tid == 0)
        atomicExch(&g_cnt[n], 0u);            // reset for next graph replay
}

// ---------------------------------------------------------------------------
// Kernel 2: out = gate[plane] * x. One block per plane, reversed plane order
// (first blocks read the planes pool touched last — partial L2 hits).
// 448 threads x 7 float4, loads front-batched, streaming stores.
// ---------------------------------------------------------------------------
__global__ __launch_bounds__(TPB) void se_scale_kernel(
    const float* __restrict__ x,
    float*       __restrict__ out)
{
    const int plane = (PLANES - 1) - blockIdx.x;
    const float g = __ldg(&g_gate[plane]);

    const float4* p = reinterpret_cast<const float4*>(x   + (size_t)plane * HW);
    float4*       q = reinterpret_cast<float4*>(out       + (size_t)plane * HW);

    float4 v[VPT];
    #pragma unroll
    for (int i = 0; i < VPT; i++)
        v[i] = p[threadIdx.x + i * TPB];

    #pragma unroll
    for (int i = 0; i < VPT; i++) {
        v[i].x *= g; v[i].y *= g; v[i].z *= g; v[i].w *= g;
        __stcs(&q[threadIdx.x + i * TPB], v[i]);
    }
}

// ---------------------------------------------------------------------------
extern "C" void kernel_launch(void* const* d_in, const int* in_sizes, int n_in,
                              void* d_out, int out_size)
{
    const float* x        = (const float*)d_in[0];
    const float* w_reduce = (const float*)d_in[1];
    const float* b_reduce = (const float*)d_in[2];
    const float* w_expand = (const float*)d_in[3];
    const float* b_expand = (const float*)d_in[4];
    float* out = (float*)d_out;

    se_pool_mlp_kernel<<<PLANES, 256>>>(x, w_reduce, b_reduce,
                                        w_expand, b_expand);
    se_scale_kernel<<<PLANES, TPB>>>(x, out);
}